// round 2
// baseline (speedup 1.0000x reference)
#include <cuda_runtime.h>
#include <math.h>

// Problem dims
#define Ss  256
#define Bb  64
#define Ii  1024
#define Hh  1024
#define H3  3072
#define Pp  1024
#define Ll  256
#define SPLITK 8
#define NEGV -1000000000.0f

// ---------------- scratch (static device allocations) ----------------
__device__ float g_GI[(size_t)Ss * Bb * H3];     // 201 MB: precomputed input gates
__device__ float g_Q [(size_t)Ss * Bb * Pp];     //  67 MB: queries
__device__ float g_GHp[SPLITK * Bb * H3];        // 6.3 MB: split-K partials of gh
__device__ float g_h [Bb * Hh];                  // running hidden state

// ---------------- generic NT GEMM: C = A * B^T (+bias) ----------------
// A: [M,K] row stride lda (K contiguous), B: [N,K] row stride ldb.
// C[m,n] -> C + m*ldc + n*cstride. grid.z offsets A/B/C by batch strides,
// and optionally selects a K-chunk (split-K) when kChunk > 0.
template<int BM,int BN,int BK,int TM,int TN>
__global__ void __launch_bounds__((BM/TM)*(BN/TN))
gemm_nt(const float* __restrict__ A, int lda, int batchA,
        const float* __restrict__ B, int ldb, int batchB,
        float* __restrict__ C, int ldc, int cstride, int batchC,
        const float* __restrict__ bias,
        int M, int N, int K, int kChunk)
{
    constexpr int TH = (BM/TM)*(BN/TN);
    __shared__ float As[BK][BM];
    __shared__ float Bs[BK][BN];

    int z = blockIdx.z;
    A += (size_t)z * batchA;
    B += (size_t)z * batchB;
    C += (size_t)z * batchC;
    int kbeg = 0, kend = K;
    if (kChunk) { kbeg = z * kChunk; kend = kbeg + kChunk; }

    int m0 = blockIdx.x * BM, n0 = blockIdx.y * BN;
    int tid = threadIdx.x;
    int tx = tid % (BN/TN), ty = tid / (BN/TN);

    float acc[TM][TN];
#pragma unroll
    for (int i = 0; i < TM; i++)
#pragma unroll
        for (int j = 0; j < TN; j++) acc[i][j] = 0.f;

    for (int k0 = kbeg; k0 < kend; k0 += BK) {
        // load A tile (vectorized float4 along K)
        {
            constexpr int V = BM * BK / 4;
#pragma unroll
            for (int v = tid; v < V; v += TH) {
                int k4 = v % (BK/4);
                int m  = v / (BK/4);
                float4 a = *reinterpret_cast<const float4*>(
                    A + (size_t)(m0 + m) * lda + k0 + k4 * 4);
                As[k4*4+0][m] = a.x; As[k4*4+1][m] = a.y;
                As[k4*4+2][m] = a.z; As[k4*4+3][m] = a.w;
            }
        }
        // load B tile
        {
            constexpr int V = BN * BK / 4;
#pragma unroll
            for (int v = tid; v < V; v += TH) {
                int k4 = v % (BK/4);
                int n  = v / (BK/4);
                float4 b = *reinterpret_cast<const float4*>(
                    B + (size_t)(n0 + n) * ldb + k0 + k4 * 4);
                Bs[k4*4+0][n] = b.x; Bs[k4*4+1][n] = b.y;
                Bs[k4*4+2][n] = b.z; Bs[k4*4+3][n] = b.w;
            }
        }
        __syncthreads();
#pragma unroll
        for (int k = 0; k < BK; k++) {
            float fa[TM], fb[TN];
#pragma unroll
            for (int i = 0; i < TM; i++) fa[i] = As[k][ty*TM + i];
#pragma unroll
            for (int j = 0; j < TN; j++) fb[j] = Bs[k][tx*TN + j];
#pragma unroll
            for (int i = 0; i < TM; i++)
#pragma unroll
                for (int j = 0; j < TN; j++)
                    acc[i][j] += fa[i] * fb[j];
        }
        __syncthreads();
    }

#pragma unroll
    for (int i = 0; i < TM; i++) {
        int m = m0 + ty*TM + i;
#pragma unroll
        for (int j = 0; j < TN; j++) {
            int n = n0 + tx*TN + j;
            float v = acc[i][j];
            if (bias) v += bias[n];
            C[(size_t)m * ldc + (size_t)n * cstride] = v;
        }
    }
}

// ---------------- NN GEMM for context: C = A * B ----------------
// A[m,k] -> A + m*ldaR + k*ldaE (strided elements), B[k,n] -> B + k*ldb + n.
template<int BM,int BN,int BK,int TM,int TN>
__global__ void __launch_bounds__((BM/TM)*(BN/TN))
gemm_nn(const float* __restrict__ A, int ldaR, int ldaE, int batchA,
        const float* __restrict__ B, int ldb, int batchB,
        float* __restrict__ C, int ldc, int batchC,
        int M, int N, int K)
{
    constexpr int TH = (BM/TM)*(BN/TN);
    __shared__ float As[BK][BM];
    __shared__ float Bs[BK][BN];

    int z = blockIdx.z;
    A += (size_t)z * batchA;
    B += (size_t)z * batchB;
    C += (size_t)z * batchC;

    int m0 = blockIdx.x * BM, n0 = blockIdx.y * BN;
    int tid = threadIdx.x;
    int tx = tid % (BN/TN), ty = tid / (BN/TN);

    float acc[TM][TN];
#pragma unroll
    for (int i = 0; i < TM; i++)
#pragma unroll
        for (int j = 0; j < TN; j++) acc[i][j] = 0.f;

    for (int k0 = 0; k0 < K; k0 += BK) {
        // A tile: scalar strided loads
#pragma unroll
        for (int e = tid; e < BM*BK; e += TH) {
            int m = e / BK, k = e % BK;
            As[k][m] = A[(size_t)(m0 + m) * ldaR + (size_t)(k0 + k) * ldaE];
        }
        // B tile: coalesced float4 along n
        {
            constexpr int V = BN * BK / 4;
#pragma unroll
            for (int v = tid; v < V; v += TH) {
                int n4 = v % (BN/4);
                int k  = v / (BN/4);
                float4 b = *reinterpret_cast<const float4*>(
                    B + (size_t)(k0 + k) * ldb + n0 + n4 * 4);
                Bs[k][n4*4+0] = b.x; Bs[k][n4*4+1] = b.y;
                Bs[k][n4*4+2] = b.z; Bs[k][n4*4+3] = b.w;
            }
        }
        __syncthreads();
#pragma unroll
        for (int k = 0; k < BK; k++) {
            float fa[TM], fb[TN];
#pragma unroll
            for (int i = 0; i < TM; i++) fa[i] = As[k][ty*TM + i];
#pragma unroll
            for (int j = 0; j < TN; j++) fb[j] = Bs[k][tx*TN + j];
#pragma unroll
            for (int i = 0; i < TM; i++)
#pragma unroll
                for (int j = 0; j < TN; j++)
                    acc[i][j] += fa[i] * fb[j];
        }
        __syncthreads();
    }

#pragma unroll
    for (int i = 0; i < TM; i++) {
        int m = m0 + ty*TM + i;
#pragma unroll
        for (int j = 0; j < TN; j++) {
            int n = n0 + tx*TN + j;
            C[(size_t)m * ldc + n] = acc[i][j];
        }
    }
}

// ---------------- elementwise kernels ----------------
__global__ void init_h_kernel(const float* __restrict__ h_init) {
    int idx = blockIdx.x * blockDim.x + threadIdx.x;   // 65536
    g_h[idx] = h_init[idx & (Hh - 1)];
}

__global__ void gru_step_kernel(const float* __restrict__ bhh,
                                const int* __restrict__ length,
                                float* __restrict__ hs, int t)
{
    int idx = blockIdx.x * blockDim.x + threadIdx.x;   // 65536
    int b = idx >> 10, j = idx & 1023;

    float ghr = bhh[j], ghz = bhh[j + Hh], ghn = bhh[j + 2*Hh];
#pragma unroll
    for (int p = 0; p < SPLITK; p++) {
        const float* gp = g_GHp + (size_t)p * Bb * H3 + (size_t)b * H3;
        ghr += gp[j]; ghz += gp[j + Hh]; ghn += gp[j + 2*Hh];
    }
    const float* GIt = g_GI + (size_t)t * Bb * H3 + (size_t)b * H3;
    float gir = GIt[j], giz = GIt[j + Hh], gin = GIt[j + 2*Hh];

    float h = g_h[idx];
    float r = 1.f / (1.f + expf(-(gir + ghr)));
    float z = 1.f / (1.f + expf(-(giz + ghz)));
    float n = tanhf(gin + r * ghn);
    float keep = (t < length[b]) ? 1.f : 0.f;
    float hn = (n + z * (h - n)) * keep;

    g_h[idx] = hn;
    hs[((size_t)t * Bb + b) * 2048 + j] = hn;
}

// masked softmax over l for each (s,b); attn layout [S, L, B]
__global__ void softmax_kernel(float* __restrict__ attn,
                               const int* __restrict__ post_length)
{
    extern __shared__ float sm[];                      // Ll*Bb floats = 64KB
    int s = blockIdx.x;
    float* base = attn + (size_t)s * Ll * Bb;
    for (int i = threadIdx.x; i < Ll * Bb; i += blockDim.x) sm[i] = base[i];
    __syncthreads();
    int b = threadIdx.x;
    if (b < Bb) {
        int plen = post_length[b];
        float m = -INFINITY;
        for (int l = 0; l < plen; l++) m = fmaxf(m, sm[l * Bb + b]);
        float sum = 0.f;
        for (int l = 0; l < plen; l++) {
            float e = expf(sm[l * Bb + b] - m);
            sm[l * Bb + b] = e;
            sum += e;
        }
        float inv = 1.f / sum;
        for (int l = 0; l < plen; l++) sm[l * Bb + b] *= inv;
        for (int l = plen; l < Ll; l++) sm[l * Bb + b] = 0.f;
    }
    __syncthreads();
    for (int i = threadIdx.x; i < Ll * Bb; i += blockDim.x) base[i] = sm[i];
}

__global__ void copy_hlast_kernel(float* __restrict__ out) {
    int idx = blockIdx.x * blockDim.x + threadIdx.x;
    out[idx] = g_h[idx];
}

// ---------------- launcher ----------------
extern "C" void kernel_launch(void* const* d_in, const int* in_sizes, int n_in,
                              void* d_out, int out_size)
{
    (void)in_sizes; (void)n_in; (void)out_size;
    const float* incoming = (const float*)d_in[0];   // [S,B,I]
    const float* post     = (const float*)d_in[1];   // [L,B,P]
    const float* h_init   = (const float*)d_in[2];   // [1,1,H]
    const float* W_ih     = (const float*)d_in[3];   // [3H,I]
    const float* W_hh     = (const float*)d_in[4];   // [3H,H]
    const float* b_ih     = (const float*)d_in[5];   // [3H]
    const float* b_hh     = (const float*)d_in[6];   // [3H]
    const float* Wq       = (const float*)d_in[7];   // [P,H]
    const float* bq       = (const float*)d_in[8];   // [P]
    const int*   length   = (const int*)d_in[9];     // [B]
    const int*   plen     = (const int*)d_in[10];    // [B]

    float* out    = (float*)d_out;
    float* h_last = out;                                       // [B,H]
    float* hs     = out + (size_t)Bb * Hh;                     // [S,B,2H]
    float* attn   = hs + (size_t)Ss * Bb * 2048;               // [S,L,B]

    float *GI, *Q, *GHp, *hbuf;
    cudaGetSymbolAddress((void**)&GI,  g_GI);
    cudaGetSymbolAddress((void**)&Q,   g_Q);
    cudaGetSymbolAddress((void**)&GHp, g_GHp);
    cudaGetSymbolAddress((void**)&hbuf, g_h);

    cudaFuncSetAttribute(softmax_kernel,
                         cudaFuncAttributeMaxDynamicSharedMemorySize, 65536);

    // 0) broadcast h_init
    init_h_kernel<<<256, 256>>>(h_init);

    // 1) GI = incoming @ W_ih^T + b_ih   (parallel over all timesteps)
    gemm_nt<128,128,8,8,8><<<dim3(Ss*Bb/128, H3/128, 1), 256>>>(
        incoming, Ii, 0,  W_ih, Ii, 0,
        GI, H3, 1, 0,  b_ih,  Ss*Bb, H3, Ii, 0);

    // 2) sequential scan: gh = h @ W_hh^T (split-K=8), then GRU elementwise
    for (int t = 0; t < Ss; t++) {
        gemm_nt<64,64,16,4,4><<<dim3(1, H3/64, SPLITK), 256>>>(
            hbuf, Hh, 0,  W_hh, Hh, 0,
            GHp, H3, 1, Bb*H3,  nullptr,  Bb, H3, Hh, Hh/SPLITK);
        gru_step_kernel<<<256, 256>>>(b_hh, length, hs, t);
    }

    // 3) Q = hs[:, :, :H] @ Wq^T + bq  (A rows have stride 2048)
    gemm_nt<128,128,8,8,8><<<dim3(Ss*Bb/128, Pp/128, 1), 256>>>(
        hs, 2048, 0,  Wq, Hh, 0,
        Q, Pp, 1, 0,  bq,  Ss*Bb, Pp, Hh, 0);

    // 4) scores[s,l,b] = Q_b[s,:] . post_b[l,:]  (batched over b via grid.z)
    gemm_nt<128,128,8,8,8><<<dim3(Ss/128, Ll/128, Bb), 256>>>(
        Q, Bb*Pp, Pp,  post, Bb*Pp, Pp,
        attn, Ll*Bb, Bb, 1,  nullptr,  Ss, Ll, Pp, 0);

    // 5) masked softmax over l, in place
    softmax_kernel<<<Ss, 256, Ll*Bb*sizeof(float)>>>(attn, plen);

    // 6) context[s,b,:] = attn_b[s,:] @ post_b  -> hs[:, :, H:2H]
    gemm_nn<64,64,16,4,4><<<dim3(Ss/64, Pp/64, Bb), 256>>>(
        attn, Ll*Bb, Bb, 1,   post, Bb*Pp, Pp,
        hs + Hh, Bb*2048, 2048,  Ss, Pp, Ll);

    // 7) h_last = final hidden state
    copy_hlast_kernel<<<256, 256>>>(h_last);
}